// round 7
// baseline (speedup 1.0000x reference)
#include <cuda_runtime.h>

// Problem constants
#define T_   24      // HIST
#define D_   256     // SKIP
#define E_   128     // END
#define O_   2       // OUT_DIM
#define KK   13      // KERNEL
#define F_   12      // future steps
#define NB   4096    // B*N nodes

#define THREADS 256
#define DC      32   // d-chunk (floats) per staging round = 8 float4
#define WROWQ   9    // ws row stride in float4 (8 data + 1 pad = 144B)
#define XROWQ   65   // xs row stride in float4 (64 data + 1 pad) -> t-rows spread banks
#define HROW    132  // h row stride in floats

typedef unsigned long long u64;

__device__ __forceinline__ void fma2(u64 &d, u64 a, u64 b) {
    // packed f32x2 fma: d.lo += a.lo*b.lo ; d.hi += a.hi*b.hi
    asm("fma.rn.f32x2 %0, %1, %2, %0;" : "+l"(d) : "l"(a), "l"(b));
}
__device__ __forceinline__ void unpack2(u64 v, float &lo, float &hi) {
    asm("mov.b64 {%0, %1}, %2;" : "=f"(lo), "=f"(hi) : "l"(v));
}

__global__ __launch_bounds__(THREADS, 3)
void tcnn_moe_kernel(const float* __restrict__ x,
                     const int*   __restrict__ labels,
                     const float* __restrict__ W1,
                     const float* __restrict__ b1,
                     const float* __restrict__ W2,
                     const float* __restrict__ b2,
                     float*       __restrict__ out)
{
    __shared__ float4 xs4[T_ * XROWQ];   // 24.96 KB: relu(x), padded; aliased as h later
    __shared__ float4 ws4[E_ * WROWQ];   // 18.4 KB: W1 chunk, [e][jq] + rotation swizzle
    __shared__ float  red[4 * 24];       // cross-warp reduction for layer 2

    const int node = blockIdx.x;
    const int tid  = threadIdx.x;
    const int lane = tid & 31;
    const int warp = tid >> 5;            // 0..7
    const int lbl  = labels[node];        // expert id 0..7

    // ---------------- stage relu(x) into padded smem (coalesced float4) ----------
    {
        const float4* xg = reinterpret_cast<const float4*>(x + (size_t)node * (T_ * D_));
        #pragma unroll
        for (int i = 0; i < (T_ * D_ / 4) / THREADS; i++) {   // 6 iters
            int idx = tid + i * THREADS;          // logical (t, dq)
            int t   = idx >> 6;
            int dq  = idx & 63;
            float4 v = xg[idx];
            v.x = fmaxf(v.x, 0.f); v.y = fmaxf(v.y, 0.f);
            v.z = fmaxf(v.z, 0.f); v.w = fmaxf(v.w, 0.f);
            xs4[t * XROWQ + dq] = v;
        }
    }

    // ---------------- layer 1: h[t][e] = relu(b1[e] + sum_d xr[t][d]*W1[e][d]) ----
    // e-SPLIT: warp w owns e in [16w,16w+16). lane: tg=lane>>2 -> t0=3*tg (24 t per warp),
    // eq=lane&3 -> e0=16w+4*eq. Each weight value read by exactly ONE warp (8-lane bcast).
    // acc[i][r]: packed {even-j sum, odd-j sum} for (t0+i, e0+r).
    u64 acc[3][4];
    #pragma unroll
    for (int i = 0; i < 3; i++)
        #pragma unroll
        for (int r = 0; r < 4; r++) acc[i][r] = 0ull;

    const float4* W1g4 = reinterpret_cast<const float4*>(W1 + (size_t)lbl * (E_ * D_));
    const int tg  = lane >> 2;
    const int eq  = lane & 3;
    const int t0  = tg * 3;
    const int e0  = warp * 16 + eq * 4;
    const int rot = (2 * warp + (eq >> 1)) & 7;   // = (e>>3)&7, uniform over this lane's 4 e rows

    for (int d0q = 0; d0q < D_ / 4; d0q += DC / 4) {     // 8 chunks of 8 float4
        __syncthreads();
        // stage W1 chunk, [e][jq] with column rotation: physical col = (jq + (e>>3)) & 7
        #pragma unroll
        for (int k = 0; k < (DC * E_ / 4) / THREADS; k++) {  // 4 iters
            int q   = tid + k * THREADS;     // 0..1023
            int e   = q >> 3;
            int jq  = q & 7;
            int col = (jq + ((e >> 3) & 7)) & 7;
            ws4[e * WROWQ + col] = W1g4[e * (D_ / 4) + d0q + jq];
        }
        __syncthreads();

        #pragma unroll
        for (int jq = 0; jq < DC / 4; jq++) {
            const int xi = d0q + jq;
            // x: 3 LDS.128, 8 distinct t-rows per warp in 8 distinct bank-groups (pad 65)
            float4 xv0 = xs4[(t0    ) * XROWQ + xi];
            float4 xv1 = xs4[(t0 + 1) * XROWQ + xi];
            float4 xv2 = xs4[(t0 + 2) * XROWQ + xi];
            u64 x0a = *reinterpret_cast<u64*>(&xv0.x), x0b = *reinterpret_cast<u64*>(&xv0.z);
            u64 x1a = *reinterpret_cast<u64*>(&xv1.x), x1b = *reinterpret_cast<u64*>(&xv1.z);
            u64 x2a = *reinterpret_cast<u64*>(&xv2.x), x2b = *reinterpret_cast<u64*>(&xv2.z);

            const int col = (jq + rot) & 7;
            #pragma unroll
            for (int r = 0; r < 4; r++) {
                float4 wv = ws4[(e0 + r) * WROWQ + col];   // 4 distinct granules/warp -> 1 wf
                u64 wa = *reinterpret_cast<u64*>(&wv.x);
                u64 wb = *reinterpret_cast<u64*>(&wv.z);
                fma2(acc[0][r], x0a, wa);  fma2(acc[0][r], x0b, wb);
                fma2(acc[1][r], x1a, wa);  fma2(acc[1][r], x1b, wb);
                fma2(acc[2][r], x2a, wa);  fma2(acc[2][r], x2b, wb);
            }
        }
    }

    __syncthreads();   // all warps done reading xs -> safe to alias as hs

    // bias + relu: h = relu(lo + hi + b1[e]); store to smem (alias of xs4)
    float* hs = reinterpret_cast<float*>(xs4);   // hs[t*HROW + e]
    {
        float4 bb = *reinterpret_cast<const float4*>(b1 + lbl * E_ + e0);
        float bba[4] = {bb.x, bb.y, bb.z, bb.w};
        #pragma unroll
        for (int i = 0; i < 3; i++) {
            float hv[4];
            #pragma unroll
            for (int r = 0; r < 4; r++) {
                float lo, hi;
                unpack2(acc[i][r], lo, hi);
                hv[r] = fmaxf(lo + hi + bba[r], 0.f);
            }
            *reinterpret_cast<float4*>(hs + (t0 + i) * HROW + e0) =
                make_float4(hv[0], hv[1], hv[2], hv[3]);
        }
    }
    __syncthreads();

    // ---------------- layer 2: out[f][o] = b2[o] + sum_{k,e} h[f+k][e]*W2[o][e][k] ----
    if (warp < 4) {
        const int e = tid;   // 0..127
        float hreg[T_];
        #pragma unroll
        for (int t = 0; t < T_; t++) hreg[t] = hs[t * HROW + e];   // consecutive -> 1 wf

        const float* W2g = W2 + (size_t)lbl * (O_ * E_ * KK);
        #pragma unroll
        for (int o = 0; o < O_; o++) {
            float w2r[KK];
            #pragma unroll
            for (int k = 0; k < KK; k++) w2r[k] = W2g[(o * E_ + e) * KK + k];

            float accf[F_];
            #pragma unroll
            for (int f = 0; f < F_; f++) {
                float s = 0.f;
                #pragma unroll
                for (int k = 0; k < KK; k++) s = fmaf(hreg[f + k], w2r[k], s);
                accf[f] = s;
            }
            #pragma unroll
            for (int f = 0; f < F_; f++) {
                float s = accf[f];
                #pragma unroll
                for (int off = 16; off > 0; off >>= 1)
                    s += __shfl_xor_sync(0xffffffffu, s, off);
                if (lane == 0) red[warp * 24 + f * 2 + o] = s;
            }
        }
    }
    __syncthreads();

    if (tid < 24) {   // tid = f*2 + o
        int o = tid & 1;
        float s = red[tid] + red[24 + tid] + red[48 + tid] + red[72 + tid];
        s += b2[lbl * O_ + o];
        out[(size_t)node * (F_ * O_) + tid] = s;
    }
}

extern "C" void kernel_launch(void* const* d_in, const int* in_sizes, int n_in,
                              void* d_out, int out_size) {
    const float* x      = (const float*)d_in[0];   // (8,512,24,256) f32
    const int*   labels = (const int*)  d_in[1];   // (8,512) i32
    const float* W1     = (const float*)d_in[2];   // (8,128,256)
    const float* b1     = (const float*)d_in[3];   // (8,128)
    const float* W2     = (const float*)d_in[4];   // (8,2,128,13)
    const float* b2     = (const float*)d_in[5];   // (8,2)
    float* out = (float*)d_out;                    // (8,512,12,2) f32

    tcnn_moe_kernel<<<NB, THREADS>>>(x, labels, W1, b1, W2, b2, out);
}

// round 9
// speedup vs baseline: 1.2747x; 1.2747x over previous
#include <cuda_runtime.h>

// Problem constants
#define T_   24      // HIST
#define D_   256     // SKIP
#define E_   128     // END
#define O_   2       // OUT_DIM
#define KK   13      // KERNEL
#define F_   12      // future steps
#define NB   4096    // B*N nodes

#define THREADS 128
#define DC      32   // d-chunk (floats) per staging round = 8 float4
#define WROWQ   9    // ws row stride in float4 (8 data + 1 pad = 144B)
#define XROWQ   65   // xs row stride in float4 (64 data + 1 pad)
#define HROW    132  // h row stride in floats

typedef unsigned long long u64;

__device__ __forceinline__ void fma2(u64 &d, u64 a, u64 b) {
    // packed f32x2 fma: d.lo += a.lo*b.lo ; d.hi += a.hi*b.hi
    asm("fma.rn.f32x2 %0, %1, %2, %0;" : "+l"(d) : "l"(a), "l"(b));
}
__device__ __forceinline__ void unpack2(u64 v, float &lo, float &hi) {
    asm("mov.b64 {%0, %1}, %2;" : "=f"(lo), "=f"(hi) : "l"(v));
}

__global__ __launch_bounds__(THREADS, 4)
void tcnn_moe_kernel(const float* __restrict__ x,
                     const int*   __restrict__ labels,
                     const float* __restrict__ W1,
                     const float* __restrict__ b1,
                     const float* __restrict__ W2,
                     const float* __restrict__ b2,
                     float*       __restrict__ out)
{
    __shared__ float4 xs4[T_ * XROWQ];   // 24.96 KB: relu(x), padded; aliased as h later
    __shared__ float4 ws4[E_ * WROWQ];   // 18.4 KB: W1 chunk, [e][jq] + rotation swizzle
    __shared__ float  red[4 * 24];       // cross-warp reduction for layer 2

    const int node = blockIdx.x;
    const int tid  = threadIdx.x;
    const int lane = tid & 31;
    const int warp = tid >> 5;            // 0..3
    const int lbl  = labels[node];        // expert id 0..7

    // ---------------- stage relu(x) into padded smem (coalesced float4) ----------
    {
        const float4* xg = reinterpret_cast<const float4*>(x + (size_t)node * (T_ * D_));
        #pragma unroll
        for (int i = 0; i < (T_ * D_ / 4) / THREADS; i++) {   // 12 iters
            int idx = tid + i * THREADS;          // logical (t, dq)
            int t   = idx >> 6;
            int dq  = idx & 63;
            float4 v = xg[idx];
            v.x = fmaxf(v.x, 0.f); v.y = fmaxf(v.y, 0.f);
            v.z = fmaxf(v.z, 0.f); v.w = fmaxf(v.w, 0.f);
            xs4[t * XROWQ + dq] = v;
        }
    }

    // ---------------- layer 1: h[t][e] = relu(b1[e] + sum_d xr[t][d]*W1[e][d]) ----
    // 4 warps: warp w owns e in [32w,32w+32). lane: eq=lane&7 -> e0=32w+4*eq;
    // tg=lane>>3 -> t0=6*tg (6 t-rows per lane). 6t x 4e register tile.
    // acc[i][r]: packed {even-j sum, odd-j sum} for (t0+i, e0+r).
    u64 acc[6][4];
    #pragma unroll
    for (int i = 0; i < 6; i++)
        #pragma unroll
        for (int r = 0; r < 4; r++) acc[i][r] = 0ull;

    const float4* W1g4 = reinterpret_cast<const float4*>(W1 + (size_t)lbl * (E_ * D_));
    const int eq  = lane & 7;
    const int tg  = lane >> 3;
    const int t0  = tg * 6;
    const int e0  = warp * 32 + eq * 4;
    const int rot = (4 * warp + (eq >> 1)) & 7;   // = ((e0+r)>>3)&7, uniform over r=0..3

    for (int d0q = 0; d0q < D_ / 4; d0q += DC / 4) {     // 8 chunks of 8 float4
        __syncthreads();
        // stage W1 chunk, [e][jq] with column rotation: physical col = (jq + (e>>3)) & 7
        #pragma unroll
        for (int k = 0; k < (DC * E_ / 4) / THREADS; k++) {  // 8 iters
            int q   = tid + k * THREADS;     // 0..1023
            int e   = q >> 3;
            int jq  = q & 7;
            int col = (jq + ((e >> 3) & 7)) & 7;
            ws4[e * WROWQ + col] = W1g4[e * (D_ / 4) + d0q + jq];
        }
        __syncthreads();

        #pragma unroll
        for (int jq = 0; jq < DC / 4; jq++) {
            const int xi = d0q + jq;
            const int col = (jq + rot) & 7;

            // weights: 4 LDS.128, each 1 wf (8 distinct granules in 8 bank-groups, 4-lane bcast)
            u64 wa[4], wb[4];
            #pragma unroll
            for (int r = 0; r < 4; r++) {
                float4 wv = ws4[(e0 + r) * WROWQ + col];
                wa[r] = *reinterpret_cast<u64*>(&wv.x);
                wb[r] = *reinterpret_cast<u64*>(&wv.z);
            }
            // x: 6 LDS.128, each 1 wf (4 distinct t-rows, 8-lane bcast)
            #pragma unroll
            for (int i = 0; i < 6; i++) {
                float4 xv = xs4[(t0 + i) * XROWQ + xi];
                u64 xa = *reinterpret_cast<u64*>(&xv.x);
                u64 xb = *reinterpret_cast<u64*>(&xv.z);
                #pragma unroll
                for (int r = 0; r < 4; r++) {
                    fma2(acc[i][r], xa, wa[r]);
                    fma2(acc[i][r], xb, wb[r]);
                }
            }
        }
    }

    __syncthreads();   // all warps done reading xs -> safe to alias as hs

    // bias + relu: h = relu(lo + hi + b1[e]); store to smem (alias of xs4)
    float* hs = reinterpret_cast<float*>(xs4);   // hs[t*HROW + e]
    {
        float4 bb = *reinterpret_cast<const float4*>(b1 + lbl * E_ + e0);
        float bba[4] = {bb.x, bb.y, bb.z, bb.w};
        #pragma unroll
        for (int i = 0; i < 6; i++) {
            float hv[4];
            #pragma unroll
            for (int r = 0; r < 4; r++) {
                float lo, hi;
                unpack2(acc[i][r], lo, hi);
                hv[r] = fmaxf(lo + hi + bba[r], 0.f);
            }
            *reinterpret_cast<float4*>(hs + (t0 + i) * HROW + e0) =
                make_float4(hv[0], hv[1], hv[2], hv[3]);
        }
    }
    __syncthreads();

    // ---------------- layer 2: out[f][o] = b2[o] + sum_{k,e} h[f+k][e]*W2[o][e][k] ----
    {
        const int e = tid;   // 0..127
        float hreg[T_];
        #pragma unroll
        for (int t = 0; t < T_; t++) hreg[t] = hs[t * HROW + e];   // consecutive -> 1 wf

        const float* W2g = W2 + (size_t)lbl * (O_ * E_ * KK);
        #pragma unroll
        for (int o = 0; o < O_; o++) {
            float w2r[KK];
            #pragma unroll
            for (int k = 0; k < KK; k++) w2r[k] = W2g[(o * E_ + e) * KK + k];

            float accf[F_];
            #pragma unroll
            for (int f = 0; f < F_; f++) {
                float s = 0.f;
                #pragma unroll
                for (int k = 0; k < KK; k++) s = fmaf(hreg[f + k], w2r[k], s);
                accf[f] = s;
            }
            #pragma unroll
            for (int f = 0; f < F_; f++) {
                float s = accf[f];
                #pragma unroll
                for (int off = 16; off > 0; off >>= 1)
                    s += __shfl_xor_sync(0xffffffffu, s, off);
                if (lane == 0) red[warp * 24 + f * 2 + o] = s;
            }
        }
    }
    __syncthreads();

    if (tid < 24) {   // tid = f*2 + o
        int o = tid & 1;
        float s = red[tid] + red[24 + tid] + red[48 + tid] + red[72 + tid];
        s += b2[lbl * O_ + o];
        out[(size_t)node * (F_ * O_) + tid] = s;
    }
}

extern "C" void kernel_launch(void* const* d_in, const int* in_sizes, int n_in,
                              void* d_out, int out_size) {
    const float* x      = (const float*)d_in[0];   // (8,512,24,256) f32
    const int*   labels = (const int*)  d_in[1];   // (8,512) i32
    const float* W1     = (const float*)d_in[2];   // (8,128,256)
    const float* b1     = (const float*)d_in[3];   // (8,128)
    const float* W2     = (const float*)d_in[4];   // (8,2,128,13)
    const float* b2     = (const float*)d_in[5];   // (8,2)
    float* out = (float*)d_out;                    // (8,512,12,2) f32

    tcnn_moe_kernel<<<NB, THREADS>>>(x, labels, W1, b1, W2, b2, out);
}